// round 13
// baseline (speedup 1.0000x reference)
#include <cuda_runtime.h>
#include <cuda_bf16.h>
#include <math_constants.h>

// Dilation2D: out[a,r] = max_{di,db in [-H,H]} input[r+di, a+db] - (di^2+db^2)/(4*scale)
// Separable, block j independent:
//   phase 1: V[y]     = max_di input[clamp(j+di), y] + h(di)
//   phase 2: out[a,j] = max_db V[a+db] + h(db)       (smem V, -inf padded)
// (clamp is exact: an OOB tap equals a legit smaller-|d| tap with smaller penalty)
//
// R12 layout: t -> (y = t>>2, q = t&3). The 4 tap-group partials for each y
// live in ADJACENT LANES of one warp -> combines are 2x shfl_xor + fmax,
// no smem partials, no barrier. ONE __syncthreads total (V handoff).
// Penalties h[i] = -d^2*inv precomputed per thread (taps past d=50 get -inf,
// making all 4 groups a uniform, branch-free 26 iterations).

#define KK   101
#define HH   (KK / 2)
#define NT   512
#define GT   26                  // 4*26 = 104 slots; d>50 slots get h=-inf
#define VPAD 204                 // phase-2 max index: 50+100+53 = 203

__global__ __launch_bounds__(NT, 1)
void dil_fused(const float* __restrict__ in,
               const float* __restrict__ scale_p,
               float* __restrict__ out) {
    __shared__ float V[VPAD];           // V row, pad cells -inf

    const int j  = blockIdx.x;          // V row == output column
    const int t  = threadIdx.x;
    const int q  = t & 3;               // tap-group 0..3 (within-warp!)
    const int y  = t >> 2;              // position 0..127
    const int yc = min(y, KK - 1);      // clamped (all accesses legal)
    const float inv = __fdividef(1.0f, 4.0f * __ldg(scale_p));

    const int dbase = -HH + GT * q;     // first tap of this thread's slice

    // ---- per-thread penalty table (off critical path; -inf kills d>HH) ----
    float h[GT];
    #pragma unroll
    for (int i = 0; i < GT; ++i) {
        const int d = dbase + i;
        h[i] = (d <= HH) ? -(float)(d * d) * inv : -CUDART_INF_F;
    }

    // pad-only V init (middle overwritten below, before the barrier)
    if (t < VPAD && (t < HH || t >= HH + KK)) V[t] = -CUDART_INF_F;

    // ---------- phase 1: 26 taps from gmem ----------
    const float* col = in + yc;
    const int jd = j + dbase;
    float a0 = -CUDART_INF_F, a1 = -CUDART_INF_F;
    float a2 = -CUDART_INF_F, a3 = -CUDART_INF_F;
    #pragma unroll
    for (int i = 0; i < GT; ++i) {
        const int rc = min(max(jd + i, 0), KK - 1);     // clamp only
        const float cand = __ldg(col + rc * KK) + h[i];
        if ((i & 3) == 0)      a0 = fmaxf(a0, cand);
        else if ((i & 3) == 1) a1 = fmaxf(a1, cand);
        else if ((i & 3) == 2) a2 = fmaxf(a2, cand);
        else                   a3 = fmaxf(a3, cand);
    }
    float v = fmaxf(fmaxf(a0, a1), fmaxf(a2, a3));
    // combine 4 groups within the warp (lanes y*4+q, q in low 2 bits)
    v = fmaxf(v, __shfl_xor_sync(0xFFFFFFFFu, v, 1));
    v = fmaxf(v, __shfl_xor_sync(0xFFFFFFFFu, v, 2));
    if (q == 0 && y < KK) V[HH + y] = v;

    __syncthreads();                    // the ONLY block barrier

    // ---------- phase 2: 26 taps from smem (base + literal offsets) ----------
    const float* vb = V + HH + yc + dbase;   // indices [0,203]
    float b0 = -CUDART_INF_F, b1 = -CUDART_INF_F;
    float b2 = -CUDART_INF_F, b3 = -CUDART_INF_F;
    #pragma unroll
    for (int i = 0; i < GT; ++i) {
        const float cand = vb[i] + h[i];
        if ((i & 3) == 0)      b0 = fmaxf(b0, cand);
        else if ((i & 3) == 1) b1 = fmaxf(b1, cand);
        else if ((i & 3) == 2) b2 = fmaxf(b2, cand);
        else                   b3 = fmaxf(b3, cand);
    }
    float w = fmaxf(fmaxf(b0, b1), fmaxf(b2, b3));
    w = fmaxf(w, __shfl_xor_sync(0xFFFFFFFFu, w, 1));
    w = fmaxf(w, __shfl_xor_sync(0xFFFFFFFFu, w, 2));
    if (q == 0 && y < KK) out[y * KK + j] = w;
}

extern "C" void kernel_launch(void* const* d_in, const int* in_sizes, int n_in,
                              void* d_out, int out_size) {
    const float* in      = (const float*)d_in[0];   // (101,101) float32
    const float* scale_p = (const float*)d_in[1];   // scalar float32
    float*       out     = (float*)d_out;           // (101,101) float32

    dil_fused<<<KK, NT>>>(in, scale_p, out);
}